// round 11
// baseline (speedup 1.0000x reference)
#include <cuda_runtime.h>
#include <cstdint>

// ZoeDepth metric depth head — tf32 mma.sync, 256-thread CTA, 2 CTAs/SM.
// Per CTA: 64 pixels. GEMM1: D1[64,128] = V @ W1^T (warp: 16 rows x 64 cols)
// h = relu(D1+b1) -> V region ; GEMM2: att[64,16] = h @ W2even^T
// Attractor: 4 threads/pixel (16 bins each). Sort: threads 0..63, bitonic-64.

namespace {
constexpr int Hc = 192, Wc = 192, SHc = 96, SWc = 96, Cc = 128, NB = 64, NA = 16;
constexpr int PIXC = 64, NTHR = 256;
constexpr float ALPHAc = 300.0f;
constexpr int LDP = 132;                      // padded row stride (floats), conflict-free
constexpr int PIXP = 65;                      // sort-staging stride, conflict-free

// smem layout (in floats)
constexpr int OFF_V   = 0;                    // 64*132  — V tile; reused as h tile
constexpr int OFF_W1  = OFF_V  + 64 * LDP;    // 128*132 — W1; reused as arr_s [64][65]
constexpr int OFF_W2E = OFF_W1 + 128 * LDP;   // 16*132
constexpr int OFF_B1S = OFF_W2E + 16 * LDP;   // 128
constexpr int OFF_B2S = OFF_B1S + 128;        // 16
constexpr int OFF_ATT = OFF_B2S + 16;         // 64*16 (byte off 110400, 16B aligned)
constexpr int SMEM_FLOATS = OFF_ATT + PIXC * 16;
constexpr int SMEM_BYTES  = SMEM_FLOATS * 4;  // 114496 B  (2 CTAs = 223.6 KB <= 228 KB)

__device__ __forceinline__ float rna_tf32(float x) {
    float r; asm("cvt.rna.tf32.f32 %0, %1;" : "=f"(r) : "f"(x)); return r;
}
__device__ __forceinline__ void mma_tf32(float* d,
                                         uint32_t a0, uint32_t a1, uint32_t a2, uint32_t a3,
                                         uint32_t b0, uint32_t b1) {
    asm volatile("mma.sync.aligned.m16n8k8.row.col.f32.tf32.tf32.f32 "
                 "{%0,%1,%2,%3}, {%4,%5,%6,%7}, {%8,%9}, {%0,%1,%2,%3};"
                 : "+f"(d[0]), "+f"(d[1]), "+f"(d[2]), "+f"(d[3])
                 : "r"(a0), "r"(a1), "r"(a2), "r"(a3), "r"(b0), "r"(b1));
}
} // namespace

__global__ __launch_bounds__(NTHR, 2)
void zoe_head_mma_kernel(const float* __restrict__ x,
                         const float* __restrict__ prev_bin,
                         const float* __restrict__ pe,
                         const float* __restrict__ w1,
                         const float* __restrict__ b1,
                         const float* __restrict__ w2,
                         const float* __restrict__ b2,
                         float* __restrict__ out,
                         int total_pixels, long long half_out)
{
    extern __shared__ float smem[];
    float* vS   = smem + OFF_V;      // later reused as h tile
    float* w1S  = smem + OFF_W1;     // later reused as sort staging
    float* w2eS = smem + OFF_W2E;
    float* b1S  = smem + OFF_B1S;
    float* b2S  = smem + OFF_B2S;
    float* attS = smem + OFF_ATT;

    const int t = threadIdx.x;
    const int wid = t >> 5, lid = t & 31;
    const int g = lid >> 2, tig = lid & 3;    // mma fragment coords
    const int HW = Hc * Wc, SHW = SHc * SWc;

    // ---- stage W1 / W2even / biases (rna -> tf32) ----
    {
        const float4* w1v = (const float4*)w1;
#pragma unroll
        for (int i = 0; i < 16; i++) {
            int idx4 = t + i * NTHR;           // 0..4095
            int o = idx4 >> 5, q = idx4 & 31;
            float4 v = w1v[idx4];
            v.x = rna_tf32(v.x); v.y = rna_tf32(v.y); v.z = rna_tf32(v.z); v.w = rna_tf32(v.w);
            *(float4*)&w1S[o * LDP + q * 4] = v;
        }
#pragma unroll
        for (int i = 0; i < 2; i++) {
            int idx4 = t + i * NTHR;           // 0..511
            int n = idx4 >> 5, q = idx4 & 31;
            float4 v = ((const float4*)w2)[(2 * n) * 32 + q];  // even output rows
            v.x = rna_tf32(v.x); v.y = rna_tf32(v.y); v.z = rna_tf32(v.z); v.w = rna_tf32(v.w);
            *(float4*)&w2eS[n * LDP + q * 4] = v;
        }
        if (t < Cc) b1S[t] = b1[t];
        if (t < NA) b2S[t] = b2[2 * t];
    }

    // ---- pixel coords (4 threads per pixel for staging/attractor) ----
    const int pxl = t >> 2;                    // 0..63
    const int q4  = t & 3;
    int p = blockIdx.x * PIXC + pxl;
    if (p >= total_pixels) p = total_pixels - 1;
    const int bIdx = p / HW;
    const int rem  = p - bIdx * HW;
    const int yy = rem / Wc, xx = rem - yy * Wc;
    const float fscale = (float)(SHc - 1) / (float)(Hc - 1);
    const float fy = yy * fscale, fx = xx * fscale;
    const int y0 = (int)fy, x0 = (int)fx;
    const int y1 = min(y0 + 1, SHc - 1), x1 = min(x0 + 1, SWc - 1);
    const float wy = fy - (float)y0, wx = fx - (float)x0;
    const float w00 = (1.f - wy) * (1.f - wx), w01 = (1.f - wy) * wx;
    const float w10 = wy * (1.f - wx),          w11 = wy * wx;
    const int i00 = y0 * SWc + x0, i01 = y0 * SWc + x1;
    const int i10 = y1 * SWc + x0, i11 = y1 * SWc + x1;

    // ---- stage V tile: v = x + bilinear(pe), rna -> tf32 (32 channels/thread) ----
    {
        const int chb = q4 * 32;
        const float* xb  = x  + (long long)bIdx * Cc * HW + (long long)chb * HW + rem;
        const float* peb = pe + (long long)bIdx * Cc * SHW + (long long)chb * SHW;
        float* vrow = vS + pxl * LDP + chb;
#pragma unroll
        for (int j4 = 0; j4 < 8; j4++) {
            float4 v;
            float* vp = (float*)&v;
#pragma unroll
            for (int u = 0; u < 4; u++) {
                int j = j4 * 4 + u;
                const float* pc = peb + j * SHW;
                float pv = w00 * __ldg(pc + i00) + w01 * __ldg(pc + i01)
                         + w10 * __ldg(pc + i10) + w11 * __ldg(pc + i11);
                vp[u] = rna_tf32(__ldg(xb + (long long)j * HW) + pv);
            }
            *(float4*)&vrow[j4 * 4] = v;
        }
    }
    __syncthreads();

    // ---- GEMM1: warp = (row-group rg 0..3, col-half ch2); 16 rows x 64 cols ----
    const int rg  = wid >> 1;
    const int ch2 = wid & 1;
    const int rA0 = (rg * 16 + g) * LDP;
    const int rA1 = rA0 + 8 * LDP;
    float acc[8][4];
#pragma unroll
    for (int j = 0; j < 8; j++)
#pragma unroll
        for (int qq = 0; qq < 4; qq++) acc[j][qq] = 0.f;

#pragma unroll 4
    for (int k = 0; k < 16; k++) {
        const int kc = k * 8 + tig;
        uint32_t a0 = __float_as_uint(vS[rA0 + kc]);
        uint32_t a1 = __float_as_uint(vS[rA1 + kc]);
        uint32_t a2 = __float_as_uint(vS[rA0 + kc + 4]);
        uint32_t a3 = __float_as_uint(vS[rA1 + kc + 4]);
#pragma unroll
        for (int j = 0; j < 8; j++) {
            const int nb = (ch2 * 64 + j * 8 + g) * LDP + kc;
            uint32_t b0 = __float_as_uint(w1S[nb]);
            uint32_t b1f = __float_as_uint(w1S[nb + 4]);
            mma_tf32(acc[j], a0, a1, a2, a3, b0, b1f);
        }
    }
    __syncthreads();   // all warps done reading vS -> safe to overwrite with h

    // ---- epilogue 1: h = rna(relu(D1 + b1)) -> h tile (vS region) ----
    {
        float* hS = vS;
#pragma unroll
        for (int j = 0; j < 8; j++) {
            const int c0 = ch2 * 64 + j * 8 + 2 * tig;
            float bb0 = b1S[c0], bb1 = b1S[c0 + 1];
            float2 h0, h1;
            h0.x = rna_tf32(fmaxf(acc[j][0] + bb0, 0.f));
            h0.y = rna_tf32(fmaxf(acc[j][1] + bb1, 0.f));
            h1.x = rna_tf32(fmaxf(acc[j][2] + bb0, 0.f));
            h1.y = rna_tf32(fmaxf(acc[j][3] + bb1, 0.f));
            *(float2*)&hS[rA0 + c0] = h0;
            *(float2*)&hS[rA1 + c0] = h1;
        }
    }
    __syncthreads();

    // ---- GEMM2: warp = (row-group rg, n-tile ch2); att[16 rows][8 cols] ----
    {
        const float* hS = vS;
        float acc2[4] = {0.f, 0.f, 0.f, 0.f};
#pragma unroll
        for (int k = 0; k < 16; k++) {
            const int kc = k * 8 + tig;
            uint32_t a0 = __float_as_uint(hS[rA0 + kc]);
            uint32_t a1 = __float_as_uint(hS[rA1 + kc]);
            uint32_t a2 = __float_as_uint(hS[rA0 + kc + 4]);
            uint32_t a3 = __float_as_uint(hS[rA1 + kc + 4]);
            const int nb = (ch2 * 8 + g) * LDP + kc;
            uint32_t b0 = __float_as_uint(w2eS[nb]);
            uint32_t b1f = __float_as_uint(w2eS[nb + 4]);
            mma_tf32(acc2, a0, a1, a2, a3, b0, b1f);
        }
        // att = relu(d + b2even) + 0.001 -> attS[pixel][16]
        const int c0 = ch2 * 8 + 2 * tig;
        float bb0 = b2S[c0], bb1 = b2S[c0 + 1];
        float2 v0, v1;
        v0.x = fmaxf(acc2[0] + bb0, 0.f) + 0.001f;
        v0.y = fmaxf(acc2[1] + bb1, 0.f) + 0.001f;
        v1.x = fmaxf(acc2[2] + bb0, 0.f) + 0.001f;
        v1.y = fmaxf(acc2[3] + bb1, 0.f) + 0.001f;
        *(float2*)&attS[(rg * 16 + g) * 16 + c0]     = v0;
        *(float2*)&attS[(rg * 16 + g + 8) * 16 + c0] = v1;
    }
    __syncthreads();

    // ---- attractor stage (4 threads per pixel, 16 bins each) ----
    float att[16];
    {
        const float4* ap = (const float4*)&attS[pxl * 16];
#pragma unroll
        for (int qq = 0; qq < 4; qq++) {
            float4 v = ap[qq];
            att[4 * qq] = v.x; att[4 * qq + 1] = v.y; att[4 * qq + 2] = v.z; att[4 * qq + 3] = v.w;
        }
    }
    float* arr_s = w1S;   // W1 tile dead — reuse as [64][PIXP]
    const float* pbb = prev_bin + (long long)bIdx * NB * SHW;
    float* out1 = out + (long long)bIdx * NB * HW + rem;
#pragma unroll 2
    for (int k = 0; k < 16; k++) {
        const int ch = q4 * 16 + k;
        const float* pc = pbb + ch * SHW;
        float bc = w00 * __ldg(pc + i00) + w01 * __ldg(pc + i01)
                 + w10 * __ldg(pc + i10) + w11 * __ldg(pc + i11);
        float s = 0.f;
#pragma unroll
        for (int i = 0; i < NA; i++) {
            float dx = att[i] - bc;
            float den = fmaf(ALPHAc * dx, dx, 1.0f);
            s += __fdividef(dx, den);
        }
        float bn = bc + s * (1.0f / 16.0f);
        out1[(long long)ch * HW] = bn;
        arr_s[ch * PIXP + pxl] = fmaf(bn, 9.999f, 0.001f);
    }
    __syncthreads();

    // ---- sort phase: threads 0..63 each sort one pixel ----
    if (t < PIXC) {
        int p2 = blockIdx.x * PIXC + t;
        if (p2 >= total_pixels) p2 = total_pixels - 1;
        const int bIdx2 = p2 / HW;
        const int rem2  = p2 - bIdx2 * HW;
        float arr[64];
#pragma unroll
        for (int ch = 0; ch < 64; ch++) arr[ch] = arr_s[ch * PIXP + t];
#pragma unroll
        for (int k = 2; k <= 64; k <<= 1) {
#pragma unroll
            for (int j = k >> 1; j > 0; j >>= 1) {
#pragma unroll
                for (int i = 0; i < 64; i++) {
                    int l = i ^ j;
                    if (l > i) {
                        float a = arr[i], bv = arr[l];
                        float mn = fminf(a, bv), mx = fmaxf(a, bv);
                        bool up = ((i & k) == 0);
                        arr[i] = up ? mn : mx;
                        arr[l] = up ? mx : mn;
                    }
                }
            }
        }
        float* out2 = out + half_out + (long long)bIdx2 * NB * HW + rem2;
#pragma unroll
        for (int ch = 0; ch < 64; ch++)
            out2[(long long)ch * HW] = fminf(fmaxf(arr[ch], 0.001f), 10.0f);
    }
}

extern "C" void kernel_launch(void* const* d_in, const int* in_sizes, int n_in,
                              void* d_out, int out_size) {
    const float* x  = (const float*)d_in[0];
    const float* pb = (const float*)d_in[1];
    const float* pe = (const float*)d_in[2];
    const float* w1 = (const float*)d_in[3];
    const float* b1 = (const float*)d_in[4];
    const float* w2 = (const float*)d_in[5];
    const float* b2 = (const float*)d_in[6];
    float* out = (float*)d_out;

    const int total_pixels = in_sizes[0] / Cc;            // 147456
    const long long half_out = (long long)out_size / 2;
    const int grid = (total_pixels + PIXC - 1) / PIXC;    // 2304

    cudaFuncSetAttribute(zoe_head_mma_kernel,
                         cudaFuncAttributeMaxDynamicSharedMemorySize, SMEM_BYTES);

    zoe_head_mma_kernel<<<grid, NTHR, SMEM_BYTES>>>(x, pb, pe, w1, b1, w2, b2, out,
                                                    total_pixels, half_out);
}

// round 12
// speedup vs baseline: 1.0352x; 1.0352x over previous
#include <cuda_runtime.h>
#include <cstdint>

// ZoeDepth metric depth head — tf32 mma.sync, 512-thread CTA (R10 skeleton).
// GEMM1: 32x32 warp tiles, paired SMEM layout (LDS.64 fragment loads).
// Attractor: packed f32x2 + pairwise-fraction (half the RCPs).
// Sort: threads 0..127, bitonic-64 (proven).

namespace {
constexpr int Hc = 192, Wc = 192, SHc = 96, SWc = 96, Cc = 128, NB = 64, NA = 16;
constexpr int PIXC = 128, NTHR = 512;
constexpr float ALPHAc = 300.0f;
constexpr int LDP2 = 136;     // paired-layout row stride (floats): conflict-free frag loads
constexpr int PIXP = 129;     // sort-staging stride

// smem layout (floats)
constexpr int OFF_V   = 0;                     // 128*136 — V tile; reused as arr_s
constexpr int OFF_W1  = OFF_V  + 128 * LDP2;   // 128*136 — W1; reused as h tile
constexpr int OFF_W2E = OFF_W1 + 128 * LDP2;   // 16*136
constexpr int OFF_B1S = OFF_W2E + 16 * LDP2;   // 128
constexpr int OFF_B2S = OFF_B1S + 128;         // 16
constexpr int OFF_ATT = OFF_B2S + 16;          // 128*16 (byte off 148544, 16B aligned)
constexpr int SMEM_FLOATS = OFF_ATT + PIXC * 16;
constexpr int SMEM_BYTES  = SMEM_FLOATS * 4;   // 156736 B

// paired slot: element channel c lives at (c>>3)*8 + (c&3)*2 + ((c>>2)&1)
__device__ __forceinline__ int pslot(int c) {
    return ((c >> 3) << 3) + ((c & 3) << 1) + ((c >> 2) & 1);
}
__device__ __forceinline__ float rna_tf32(float x) {
    float r; asm("cvt.rna.tf32.f32 %0, %1;" : "=f"(r) : "f"(x)); return r;
}
__device__ __forceinline__ float rcpa(float x) {
    float r; asm("rcp.approx.f32 %0, %1;" : "=f"(r) : "f"(x)); return r;
}
__device__ __forceinline__ unsigned long long pack2(float lo, float hi) {
    unsigned long long r;
    asm("mov.b64 %0, {%1, %2};" : "=l"(r) : "f"(lo), "f"(hi));
    return r;
}
__device__ __forceinline__ void unpack2(unsigned long long v, float& lo, float& hi) {
    asm("mov.b64 {%0, %1}, %2;" : "=f"(lo), "=f"(hi) : "l"(v));
}
// d = a*b + c, packed f32x2 (proven on this harness in rounds 4-5)
__device__ __forceinline__ unsigned long long fma2(unsigned long long a,
                                                   unsigned long long b,
                                                   unsigned long long c) {
    unsigned long long d;
    asm("fma.rn.f32x2 %0, %1, %2, %3;" : "=l"(d) : "l"(a), "l"(b), "l"(c));
    return d;
}
__device__ __forceinline__ void mma_tf32(float* d,
                                         uint32_t a0, uint32_t a1, uint32_t a2, uint32_t a3,
                                         uint32_t b0, uint32_t b1) {
    asm volatile("mma.sync.aligned.m16n8k8.row.col.f32.tf32.tf32.f32 "
                 "{%0,%1,%2,%3}, {%4,%5,%6,%7}, {%8,%9}, {%0,%1,%2,%3};"
                 : "+f"(d[0]), "+f"(d[1]), "+f"(d[2]), "+f"(d[3])
                 : "r"(a0), "r"(a1), "r"(a2), "r"(a3), "r"(b0), "r"(b1));
}
__device__ __forceinline__ uint32_t fu(float x) { return __float_as_uint(x); }
} // namespace

__global__ __launch_bounds__(NTHR, 1)
void zoe_head_mma_kernel(const float* __restrict__ x,
                         const float* __restrict__ prev_bin,
                         const float* __restrict__ pe,
                         const float* __restrict__ w1,
                         const float* __restrict__ b1,
                         const float* __restrict__ w2,
                         const float* __restrict__ b2,
                         float* __restrict__ out,
                         int total_pixels, long long half_out)
{
    extern __shared__ float smem[];
    float* vS   = smem + OFF_V;      // later reused as sort staging
    float* w1S  = smem + OFF_W1;     // later reused as h tile
    float* w2eS = smem + OFF_W2E;
    float* b1S  = smem + OFF_B1S;
    float* b2S  = smem + OFF_B2S;
    float* attS = smem + OFF_ATT;

    const int t = threadIdx.x;
    const int wid = t >> 5, lid = t & 31;
    const int g = lid >> 2, tig = lid & 3;    // mma fragment coords
    const int HW = Hc * Wc, SHW = SHc * SWc;

    // ---- stage W1 / W2even / biases into paired tf32 layout ----
    {
        const float4* w1v = (const float4*)w1;
#pragma unroll
        for (int i = 0; i < 4; i++) {
            int idx8 = t + i * NTHR;          // 0..2047: row o, 8-channel group g8
            int o = idx8 >> 4, g8 = idx8 & 15;
            float4 lo = w1v[o * 32 + g8 * 2];
            float4 hi = w1v[o * 32 + g8 * 2 + 1];
            float* dst = &w1S[o * LDP2 + g8 * 8];
            *(float2*)&dst[0] = make_float2(rna_tf32(lo.x), rna_tf32(hi.x));
            *(float2*)&dst[2] = make_float2(rna_tf32(lo.y), rna_tf32(hi.y));
            *(float2*)&dst[4] = make_float2(rna_tf32(lo.z), rna_tf32(hi.z));
            *(float2*)&dst[6] = make_float2(rna_tf32(lo.w), rna_tf32(hi.w));
        }
        if (t < 256) {                         // 16 rows x 16 groups
            int o = t >> 4, g8 = t & 15;
            const float4* w2v = (const float4*)w2;
            float4 lo = w2v[(2 * o) * 32 + g8 * 2];      // even output rows
            float4 hi = w2v[(2 * o) * 32 + g8 * 2 + 1];
            float* dst = &w2eS[o * LDP2 + g8 * 8];
            *(float2*)&dst[0] = make_float2(rna_tf32(lo.x), rna_tf32(hi.x));
            *(float2*)&dst[2] = make_float2(rna_tf32(lo.y), rna_tf32(hi.y));
            *(float2*)&dst[4] = make_float2(rna_tf32(lo.z), rna_tf32(hi.z));
            *(float2*)&dst[6] = make_float2(rna_tf32(lo.w), rna_tf32(hi.w));
        }
        if (t < Cc) b1S[t] = b1[t];
        if (t < NA) b2S[t] = b2[2 * t];
    }

    // ---- pixel coords (4 threads per pixel for staging/attractor) ----
    const int pxl = t >> 2;
    const int q4  = t & 3;
    int p = blockIdx.x * PIXC + pxl;
    if (p >= total_pixels) p = total_pixels - 1;
    const int bIdx = p / HW;
    const int rem  = p - bIdx * HW;
    const int yy = rem / Wc, xx = rem - yy * Wc;
    const float fscale = (float)(SHc - 1) / (float)(Hc - 1);
    const float fy = yy * fscale, fx = xx * fscale;
    const int y0 = (int)fy, x0 = (int)fx;
    const int y1 = min(y0 + 1, SHc - 1), x1 = min(x0 + 1, SWc - 1);
    const float wy = fy - (float)y0, wx = fx - (float)x0;
    const float w00 = (1.f - wy) * (1.f - wx), w01 = (1.f - wy) * wx;
    const float w10 = wy * (1.f - wx),          w11 = wy * wx;
    const int i00 = y0 * SWc + x0, i01 = y0 * SWc + x1;
    const int i10 = y1 * SWc + x0, i11 = y1 * SWc + x1;

    // ---- stage V tile: v = x + bilinear(pe), rna->tf32, paired layout ----
    {
        const int chb = q4 * 32;
        const float* xb  = x  + (long long)bIdx * Cc * HW + rem;
        const float* peb = pe + (long long)bIdx * Cc * SHW;
        float* vrow = vS + pxl * LDP2;
#pragma unroll
        for (int g8l = 0; g8l < 4; g8l++) {
            const int cg = chb + g8l * 8;
            float v[8];
#pragma unroll
            for (int u = 0; u < 8; u++) {
                const float* pc = peb + (long long)(cg + u) * SHW;
                float pv = w00 * __ldg(pc + i00) + w01 * __ldg(pc + i01)
                         + w10 * __ldg(pc + i10) + w11 * __ldg(pc + i11);
                v[u] = rna_tf32(__ldg(xb + (long long)(cg + u) * HW) + pv);
            }
            float* dst = &vrow[(q4 * 4 + g8l) * 8];
            *(float2*)&dst[0] = make_float2(v[0], v[4]);
            *(float2*)&dst[2] = make_float2(v[1], v[5]);
            *(float2*)&dst[4] = make_float2(v[2], v[6]);
            *(float2*)&dst[6] = make_float2(v[3], v[7]);
        }
    }
    __syncthreads();

    // ---- GEMM1: warp = 32x32 tile; rg=wid>>2 rows, cg=wid&3 cols ----
    const int rg = wid >> 2, cgw = wid & 3;
    const int r0 = rg * 32, c0 = cgw * 32;
    float acc[2][4][4];
#pragma unroll
    for (int rt = 0; rt < 2; rt++)
#pragma unroll
        for (int ct = 0; ct < 4; ct++)
#pragma unroll
            for (int qq = 0; qq < 4; qq++) acc[rt][ct][qq] = 0.f;

#pragma unroll 4
    for (int k = 0; k < 16; k++) {
        const int kb = k * 8 + 2 * tig;
        float2 A0 = *(const float2*)&vS[(r0 + g) * LDP2 + kb];        // (a0,a2) rows r0+g
        float2 A1 = *(const float2*)&vS[(r0 + g + 8) * LDP2 + kb];    // (a1,a3)
        float2 A2 = *(const float2*)&vS[(r0 + 16 + g) * LDP2 + kb];
        float2 A3 = *(const float2*)&vS[(r0 + 24 + g) * LDP2 + kb];
#pragma unroll
        for (int ct = 0; ct < 4; ct++) {
            float2 B = *(const float2*)&w1S[(c0 + ct * 8 + g) * LDP2 + kb];
            mma_tf32(acc[0][ct], fu(A0.x), fu(A1.x), fu(A0.y), fu(A1.y), fu(B.x), fu(B.y));
            mma_tf32(acc[1][ct], fu(A2.x), fu(A3.x), fu(A2.y), fu(A3.y), fu(B.x), fu(B.y));
        }
    }
    __syncthreads();   // all warps done reading w1S -> safe to overwrite with h

    // ---- epilogue 1: h = rna(relu(D1+b1)) -> h tile (w1S region, paired) ----
    {
        float* hS = w1S;
#pragma unroll
        for (int rt = 0; rt < 2; rt++) {
            const int ra = (r0 + rt * 16 + g) * LDP2;
            const int rb = ra + 8 * LDP2;
#pragma unroll
            for (int ct = 0; ct < 4; ct++) {
                const int c = c0 + ct * 8 + 2 * tig;
                const float bb0 = b1S[c], bb1 = b1S[c + 1];
                const int s0 = pslot(c), s1 = pslot(c + 1);
                hS[ra + s0] = rna_tf32(fmaxf(acc[rt][ct][0] + bb0, 0.f));
                hS[ra + s1] = rna_tf32(fmaxf(acc[rt][ct][1] + bb1, 0.f));
                hS[rb + s0] = rna_tf32(fmaxf(acc[rt][ct][2] + bb0, 0.f));
                hS[rb + s1] = rna_tf32(fmaxf(acc[rt][ct][3] + bb1, 0.f));
            }
        }
    }
    __syncthreads();

    // ---- GEMM2: warp = (row-group rg2 of 16, n-tile ch2); att[16][8] ----
    {
        const float* hS = w1S;
        const int rg2 = wid >> 1, ch2 = wid & 1;
        const int rA0 = (rg2 * 16 + g) * LDP2;
        const int rA1 = rA0 + 8 * LDP2;
        float acc2[4] = {0.f, 0.f, 0.f, 0.f};
#pragma unroll
        for (int k = 0; k < 16; k++) {
            const int kb = k * 8 + 2 * tig;
            float2 HA0 = *(const float2*)&hS[rA0 + kb];
            float2 HA1 = *(const float2*)&hS[rA1 + kb];
            float2 B = *(const float2*)&w2eS[(ch2 * 8 + g) * LDP2 + kb];
            mma_tf32(acc2, fu(HA0.x), fu(HA1.x), fu(HA0.y), fu(HA1.y), fu(B.x), fu(B.y));
        }
        const int c0a = ch2 * 8 + 2 * tig;
        const float bb0 = b2S[c0a], bb1 = b2S[c0a + 1];
        float2 v0, v1;
        v0.x = fmaxf(acc2[0] + bb0, 0.f) + 0.001f;
        v0.y = fmaxf(acc2[1] + bb1, 0.f) + 0.001f;
        v1.x = fmaxf(acc2[2] + bb0, 0.f) + 0.001f;
        v1.y = fmaxf(acc2[3] + bb1, 0.f) + 0.001f;
        *(float2*)&attS[(rg2 * 16 + g) * 16 + c0a]     = v0;
        *(float2*)&attS[(rg2 * 16 + g + 8) * 16 + c0a] = v1;
    }
    __syncthreads();

    // ---- attractor stage: packed f32x2, pairwise fractions, 4 thr/pixel ----
    unsigned long long atp[16];
    {
        const float4* ap = (const float4*)&attS[pxl * 16];
#pragma unroll
        for (int qq = 0; qq < 4; qq++) {
            float4 v = ap[qq];
            atp[4 * qq + 0] = pack2(v.x, v.x);
            atp[4 * qq + 1] = pack2(v.y, v.y);
            atp[4 * qq + 2] = pack2(v.z, v.z);
            atp[4 * qq + 3] = pack2(v.w, v.w);
        }
    }
    const unsigned long long ONE2  = pack2(1.f, 1.f);
    const unsigned long long ZERO2 = pack2(0.f, 0.f);
    const unsigned long long AL2   = pack2(ALPHAc, ALPHAc);

    float* arr_s = vS;   // V tile dead — reuse as [64][PIXP]
    const float* pbb = prev_bin + (long long)bIdx * NB * SHW;
    float* out1 = out + (long long)bIdx * NB * HW + rem;
#pragma unroll 1
    for (int j = 0; j < 8; j++) {
        const int ch0 = q4 * 16 + 2 * j;
        const float* pc0 = pbb + (long long)ch0 * SHW;
        const float* pc1 = pc0 + SHW;
        float bc0 = w00 * __ldg(pc0 + i00) + w01 * __ldg(pc0 + i01)
                  + w10 * __ldg(pc0 + i10) + w11 * __ldg(pc0 + i11);
        float bc1 = w00 * __ldg(pc1 + i00) + w01 * __ldg(pc1 + i01)
                  + w10 * __ldg(pc1 + i10) + w11 * __ldg(pc1 + i11);
        const unsigned long long negb = pack2(-bc0, -bc1);
        unsigned long long s2 = ZERO2;
#pragma unroll
        for (int i = 0; i < 16; i += 2) {
            unsigned long long dx0 = fma2(atp[i],     ONE2, negb);   // att_i - bc
            unsigned long long t0  = fma2(dx0, AL2, ZERO2);          // 300*dx
            unsigned long long dn0 = fma2(t0, dx0, ONE2);            // 1+300dx^2
            unsigned long long dx1 = fma2(atp[i + 1], ONE2, negb);
            unsigned long long t1  = fma2(dx1, AL2, ZERO2);
            unsigned long long dn1 = fma2(t1, dx1, ONE2);
            unsigned long long num = fma2(dx0, dn1, ZERO2);
            num = fma2(dx1, dn0, num);                               // dx0*dn1 + dx1*dn0
            unsigned long long dpr = fma2(dn0, dn1, ZERO2);          // dn0*dn1
            float dl, dh;
            unpack2(dpr, dl, dh);
            unsigned long long rp = pack2(rcpa(dl), rcpa(dh));
            s2 = fma2(num, rp, s2);                                  // += num/dpr
        }
        float s0, s1;
        unpack2(s2, s0, s1);
        float bn0 = bc0 + s0 * (1.0f / 16.0f);
        float bn1 = bc1 + s1 * (1.0f / 16.0f);
        out1[(long long)ch0 * HW]       = bn0;
        out1[(long long)(ch0 + 1) * HW] = bn1;
        arr_s[ch0 * PIXP + pxl]       = fmaf(bn0, 9.999f, 0.001f);
        arr_s[(ch0 + 1) * PIXP + pxl] = fmaf(bn1, 9.999f, 0.001f);
    }
    __syncthreads();

    // ---- sort phase: threads 0..127 each sort one pixel ----
    if (t < PIXC) {
        int p2 = blockIdx.x * PIXC + t;
        if (p2 >= total_pixels) p2 = total_pixels - 1;
        const int bIdx2 = p2 / HW;
        const int rem2  = p2 - bIdx2 * HW;
        float arr[64];
#pragma unroll
        for (int ch = 0; ch < 64; ch++) arr[ch] = arr_s[ch * PIXP + t];
#pragma unroll
        for (int k = 2; k <= 64; k <<= 1) {
#pragma unroll
            for (int j = k >> 1; j > 0; j >>= 1) {
#pragma unroll
                for (int i = 0; i < 64; i++) {
                    int l = i ^ j;
                    if (l > i) {
                        float a = arr[i], bv = arr[l];
                        float mn = fminf(a, bv), mx = fmaxf(a, bv);
                        bool up = ((i & k) == 0);
                        arr[i] = up ? mn : mx;
                        arr[l] = up ? mx : mn;
                    }
                }
            }
        }
        float* out2 = out + half_out + (long long)bIdx2 * NB * HW + rem2;
#pragma unroll
        for (int ch = 0; ch < 64; ch++)
            out2[(long long)ch * HW] = fminf(fmaxf(arr[ch], 0.001f), 10.0f);
    }
}

extern "C" void kernel_launch(void* const* d_in, const int* in_sizes, int n_in,
                              void* d_out, int out_size) {
    const float* x  = (const float*)d_in[0];
    const float* pb = (const float*)d_in[1];
    const float* pe = (const float*)d_in[2];
    const float* w1 = (const float*)d_in[3];
    const float* b1 = (const float*)d_in[4];
    const float* w2 = (const float*)d_in[5];
    const float* b2 = (const float*)d_in[6];
    float* out = (float*)d_out;

    const int total_pixels = in_sizes[0] / Cc;            // 147456
    const long long half_out = (long long)out_size / 2;
    const int grid = (total_pixels + PIXC - 1) / PIXC;    // 1152

    cudaFuncSetAttribute(zoe_head_mma_kernel,
                         cudaFuncAttributeMaxDynamicSharedMemorySize, SMEM_BYTES);

    zoe_head_mma_kernel<<<grid, NTHR, SMEM_BYTES>>>(x, pb, pe, w1, b1, w2, b2, out,
                                                    total_pixels, half_out);
}